// round 9
// baseline (speedup 1.0000x reference)
#include <cuda_runtime.h>
#include <cuda_bf16.h>
#include <math.h>
#include <stdint.h>

// STAttn fused, GB300 sm_103a. Round 9 submission (tf32 design; hardware
// contact still pending after 5x broker timeouts): tf32 mma.sync,
// zero-conversion x path.
// B=32,T=32 (BT=1024), N=64, D=512, H=64, OUT=256.
//
// prep  : split ue_w, fc1_w into fp32 hi (tf32-grid exact) + lo (residual).
// main  : per-bt CTA. x cp.async'd raw fp32 into smem (K-chunk double-buffered),
//         h = x@(Whi+Wlo) via 2 tf32 products (x truncation ~2^-11 is the only
//         error). Epilogue: bias+lrelu+w_w dot -> softmax(N) -> exact fp32
//         pooling -> attr split hi/lo fp32 to global.
// fc    : 64 CTAs, 64x64 tiles, 3 tf32 products (Ah*Bh + Ah*Bl + Al*Bh),
//         writes out[t][b][o].

#define NB 64
#define DD 512
#define HH 64
#define OUTC 256
#define BT 1024

#define XP 516                 // x smem pitch (floats): 516%32=4 -> conflict-free frags
#define BP 68                  // weight-chunk pitch (floats): 68%32=4 -> conflict-free
#define PLANE (64 * BP)        // 4352 floats: one hi or lo plane of a 64x64 chunk
#define WBUF (2 * PLANE)       // hi+lo

// main smem (floats): Xs[64*516] | WB[2*WBUF] | bias 64 | ww 64 | e 64 | a 64
#define XS_F   0
#define WB_F   (NB * XP)                    // 33024
#define MISC_F (WB_F + 2 * WBUF)            // 50432
#define SMEM_MAIN_BYTES ((MISC_F + 256) * 4)
// fc smem: A bufs 2*WBUF | B bufs 2*WBUF
#define FA_F 0
#define FB_F (2 * WBUF)
#define SMEM_FC_BYTES (4 * WBUF * 4)

#define TF32_MASK 0xFFFFE000u

__device__ __align__(16) float g_uw_h[HH * DD];
__device__ __align__(16) float g_uw_l[HH * DD];
__device__ __align__(16) float g_fw_h[OUTC * DD];
__device__ __align__(16) float g_fw_l[OUTC * DD];
__device__ __align__(16) float g_attr_h[BT * DD];
__device__ __align__(16) float g_attr_l[BT * DD];

// ---------------- helpers ----------------
__device__ __forceinline__ uint32_t fbits(float f) { return __float_as_uint(f); }
__device__ __forceinline__ void cp_async16(uint32_t s, const void* g) {
    asm volatile("cp.async.cg.shared.global [%0], [%1], 16;\n" :: "r"(s), "l"(g));
}
__device__ __forceinline__ void cp_commit() { asm volatile("cp.async.commit_group;\n"); }
template <int N> __device__ __forceinline__ void cp_wait() {
    asm volatile("cp.async.wait_group %0;\n" :: "n"(N));
}
__device__ __forceinline__ uint32_t smem_u32(const void* p) {
    uint32_t a;
    asm("{ .reg .u64 t; cvta.to.shared.u64 t, %1; cvt.u32.u64 %0, t; }" : "=r"(a) : "l"(p));
    return a;
}
// m16n8k8 tf32: A row-major (4 regs), B col-major (2 regs), C/D fp32 (4 regs)
__device__ __forceinline__ void mma_tf32(float* d, const uint32_t* a, uint32_t b0, uint32_t b1) {
    asm volatile(
        "mma.sync.aligned.m16n8k8.row.col.f32.tf32.tf32.f32 "
        "{%0,%1,%2,%3}, {%4,%5,%6,%7}, {%8,%9}, {%0,%1,%2,%3};\n"
        : "+f"(d[0]), "+f"(d[1]), "+f"(d[2]), "+f"(d[3])
        : "r"(a[0]), "r"(a[1]), "r"(a[2]), "r"(a[3]), "r"(b0), "r"(b1));
}

// ---------------- prep: split weights into tf32-exact hi + residual lo ----------------
__global__ __launch_bounds__(256)
void prep_split(const float* __restrict__ ue_w, const float* __restrict__ fc1_w) {
    int i = blockIdx.x * 256 + threadIdx.x;
    const int n_ue = HH * DD;            // 32768
    const int n_fc = OUTC * DD;          // 131072
    float f;
    float *dh, *dl;
    int k;
    if (i < n_ue) { f = ue_w[i]; dh = g_uw_h; dl = g_uw_l; k = i; }
    else if (i < n_ue + n_fc) { k = i - n_ue; f = fc1_w[k]; dh = g_fw_h; dl = g_fw_l; }
    else return;
    float hi = __uint_as_float(fbits(f) & TF32_MASK);
    dh[k] = hi;
    dl[k] = f - hi;       // exact residual, <= 13 mantissa bits
}

// ---------------- kernel 1: per-bt CTA ----------------
__global__ __launch_bounds__(256, 1)
void stattn_main(const float* __restrict__ x,
                 const float* __restrict__ ue_b,
                 const float* __restrict__ be,
                 const float* __restrict__ w_w) {
    extern __shared__ float sf[];
    float* Xs = sf + XS_F;
    float* WB = sf + WB_F;
    float* bias_s = sf + MISC_F;
    float* ww_s   = sf + MISC_F + 64;
    float* e_s    = sf + MISC_F + 128;
    float* a_s    = sf + MISC_F + 192;

    const int tid = threadIdx.x, lane = tid & 31, warp = tid >> 5;
    const int wm = warp & 1;        // m-split 2 (32 rows each)
    const int wn = warp >> 1;       // n-split 4 (16 cols each)
    const int ld = lane >> 2, l4 = lane & 3;
    const int bt = blockIdx.x;

    if (tid < 64) {
        e_s[tid] = 0.0f;
        bias_s[tid] = ue_b[tid] + be[tid];
        ww_s[tid] = w_w[tid];
    }

    const float* xg = x + (size_t)bt * (NB * DD);

    auto load_x = [&](int kc) {   // 64 rows x 64 floats = 1024 16B-granules
#pragma unroll
        for (int it = 0; it < 4; ++it) {
            int idx = tid + it * 256;
            int n = idx >> 4, g = idx & 15;
            cp_async16(smem_u32(Xs + n * XP + kc * 64 + g * 4),
                       xg + n * DD + kc * 64 + g * 4);
        }
    };
    auto load_w = [&](int kc, int buf) {  // 2 planes x 64 rows x 16 granules
        float* Wb = WB + buf * WBUF;
#pragma unroll
        for (int it = 0; it < 8; ++it) {
            int idx = tid + it * 256;
            int p = idx >> 10, r = idx & 1023;
            int j = r >> 4, g = r & 15;
            const float* src = (p ? g_uw_l : g_uw_h) + j * DD + kc * 64 + g * 4;
            cp_async16(smem_u32(Wb + p * PLANE + j * BP + g * 4), src);
        }
    };

    load_x(0); load_w(0, 0); cp_commit();
    load_x(1); load_w(1, 1); cp_commit();

    float acc[2][2][4];
#pragma unroll
    for (int a = 0; a < 2; ++a)
#pragma unroll
        for (int b = 0; b < 2; ++b)
#pragma unroll
            for (int c = 0; c < 4; ++c) acc[a][b][c] = 0.0f;

    for (int kc = 0; kc < 8; ++kc) {
        if (kc < 7) cp_wait<1>(); else cp_wait<0>();
        __syncthreads();
        const float* Wc = WB + (kc & 1) * WBUF;

#pragma unroll
        for (int ks = 0; ks < 8; ++ks) {
            const float* xb = Xs + kc * 64 + ks * 8 + l4;
            uint32_t a[2][4];
#pragma unroll
            for (int mt = 0; mt < 2; ++mt) {
                const int r0 = (wm * 32 + mt * 16 + ld) * XP;
                a[mt][0] = fbits(xb[r0]);
                a[mt][1] = fbits(xb[r0 + 8 * XP]);
                a[mt][2] = fbits(xb[r0 + 4]);
                a[mt][3] = fbits(xb[r0 + 8 * XP + 4]);
            }
#pragma unroll
            for (int nt = 0; nt < 2; ++nt) {
                const float* wb = Wc + (wn * 16 + nt * 8 + ld) * BP + ks * 8 + l4;
                uint32_t bh0 = fbits(wb[0]), bh1 = fbits(wb[4]);
                uint32_t bl0 = fbits(wb[PLANE]), bl1 = fbits(wb[PLANE + 4]);
#pragma unroll
                for (int mt = 0; mt < 2; ++mt) {
                    mma_tf32(acc[mt][nt], a[mt], bh0, bh1);   // x * W_hi
                    mma_tf32(acc[mt][nt], a[mt], bl0, bl1);   // x * W_lo
                }
            }
        }
        __syncthreads();
        if (kc + 2 < 8) { load_x(kc + 2); load_w(kc + 2, kc & 1); cp_commit(); }
    }

    // ---- epilogue: bias + leaky_relu(0.2) + dot w_w -> e[64] ----
#pragma unroll
    for (int mt = 0; mt < 2; ++mt) {
        float pe0 = 0.0f, pe1 = 0.0f;   // rows r, r+8
#pragma unroll
        for (int nt = 0; nt < 2; ++nt) {
            const int j = wn * 16 + nt * 8 + l4 * 2;
            float v;
            v = acc[mt][nt][0] + bias_s[j];     v = (v < 0.0f) ? 0.2f * v : v; pe0 = fmaf(ww_s[j],     v, pe0);
            v = acc[mt][nt][1] + bias_s[j + 1]; v = (v < 0.0f) ? 0.2f * v : v; pe0 = fmaf(ww_s[j + 1], v, pe0);
            v = acc[mt][nt][2] + bias_s[j];     v = (v < 0.0f) ? 0.2f * v : v; pe1 = fmaf(ww_s[j],     v, pe1);
            v = acc[mt][nt][3] + bias_s[j + 1]; v = (v < 0.0f) ? 0.2f * v : v; pe1 = fmaf(ww_s[j + 1], v, pe1);
        }
        // reduce over the 4 lanes sharing a row (lane&3), then one atomic per group
        pe0 += __shfl_xor_sync(0xffffffffu, pe0, 1);
        pe0 += __shfl_xor_sync(0xffffffffu, pe0, 2);
        pe1 += __shfl_xor_sync(0xffffffffu, pe1, 1);
        pe1 += __shfl_xor_sync(0xffffffffu, pe1, 2);
        if (l4 == 0) {
            const int r = wm * 32 + mt * 16 + ld;
            atomicAdd(&e_s[r], pe0);
            atomicAdd(&e_s[r + 8], pe1);
        }
    }
    __syncthreads();

    // ---- softmax over N=64 (w_b is softmax-invariant, dropped) ----
    if (warp == 0) {
        float e0 = e_s[lane], e1 = e_s[lane + 32];
        float mx = fmaxf(e0, e1);
#pragma unroll
        for (int o = 16; o; o >>= 1) mx = fmaxf(mx, __shfl_xor_sync(0xffffffffu, mx, o));
        float x0 = expf(e0 - mx), x1 = expf(e1 - mx);
        float s = x0 + x1;
#pragma unroll
        for (int o = 16; o; o >>= 1) s += __shfl_xor_sync(0xffffffffu, s, o);
        float inv = 1.0f / s;
        a_s[lane] = x0 * inv;
        a_s[lane + 32] = x1 * inv;
    }
    __syncthreads();

    // ---- pooling over exact fp32 x; store attr as exact hi/lo fp32 ----
    {
        const int d0 = 2 * tid;
        float s0 = 0.0f, s1 = 0.0f;
#pragma unroll 8
        for (int n = 0; n < NB; ++n) {
            float2 v = *reinterpret_cast<const float2*>(Xs + n * XP + d0);
            float an = a_s[n];
            s0 = fmaf(an, v.x, s0);
            s1 = fmaf(an, v.y, s1);
        }
        float h0 = __uint_as_float(fbits(s0) & TF32_MASK);
        float h1 = __uint_as_float(fbits(s1) & TF32_MASK);
        *reinterpret_cast<float2*>(g_attr_h + bt * DD + d0) = make_float2(h0, h1);
        *reinterpret_cast<float2*>(g_attr_l + bt * DD + d0) = make_float2(s0 - h0, s1 - h1);
    }
}

// ---------------- kernel 2: fc = attr @ fc1_w^T + b, out[t][b][o] ----------------
__global__ __launch_bounds__(256, 1)
void stattn_fc(const float* __restrict__ fc1_b, float* __restrict__ out) {
    extern __shared__ float sf[];
    float* AB = sf + FA_F;     // 2 bufs x (hi plane | lo plane)
    float* BB = sf + FB_F;

    const int tid = threadIdx.x, lane = tid & 31, warp = tid >> 5;
    const int wm = warp & 1, wn = warp >> 1;
    const int ld = lane >> 2, l4 = lane & 3;
    const int m0 = blockIdx.x * 64;   // bt tile
    const int n0 = blockIdx.y * 64;   // out-col tile

    auto load_a = [&](int kc, int buf) {
        float* Ab = AB + buf * WBUF;
#pragma unroll
        for (int it = 0; it < 8; ++it) {
            int idx = tid + it * 256;
            int p = idx >> 10, r = idx & 1023;
            int j = r >> 4, g = r & 15;
            const float* src = (p ? g_attr_l : g_attr_h) + (m0 + j) * DD + kc * 64 + g * 4;
            cp_async16(smem_u32(Ab + p * PLANE + j * BP + g * 4), src);
        }
    };
    auto load_b = [&](int kc, int buf) {
        float* Bb = BB + buf * WBUF;
#pragma unroll
        for (int it = 0; it < 8; ++it) {
            int idx = tid + it * 256;
            int p = idx >> 10, r = idx & 1023;
            int j = r >> 4, g = r & 15;
            const float* src = (p ? g_fw_l : g_fw_h) + (n0 + j) * DD + kc * 64 + g * 4;
            cp_async16(smem_u32(Bb + p * PLANE + j * BP + g * 4), src);
        }
    };

    load_a(0, 0); load_b(0, 0); cp_commit();
    load_a(1, 1); load_b(1, 1); cp_commit();

    float acc[2][2][4];
#pragma unroll
    for (int a = 0; a < 2; ++a)
#pragma unroll
        for (int b = 0; b < 2; ++b)
#pragma unroll
            for (int c = 0; c < 4; ++c) acc[a][b][c] = 0.0f;

    for (int kc = 0; kc < 8; ++kc) {
        if (kc < 7) cp_wait<1>(); else cp_wait<0>();
        __syncthreads();
        const float* Ac = AB + (kc & 1) * WBUF;
        const float* Bc = BB + (kc & 1) * WBUF;

#pragma unroll
        for (int ks = 0; ks < 8; ++ks) {
            uint32_t ah[2][4], al[2][4];
#pragma unroll
            for (int mt = 0; mt < 2; ++mt) {
                const float* ab = Ac + (wm * 32 + mt * 16 + ld) * BP + ks * 8 + l4;
                ah[mt][0] = fbits(ab[0]);
                ah[mt][1] = fbits(ab[8 * BP]);
                ah[mt][2] = fbits(ab[4]);
                ah[mt][3] = fbits(ab[8 * BP + 4]);
                al[mt][0] = fbits(ab[PLANE]);
                al[mt][1] = fbits(ab[PLANE + 8 * BP]);
                al[mt][2] = fbits(ab[PLANE + 4]);
                al[mt][3] = fbits(ab[PLANE + 8 * BP + 4]);
            }
#pragma unroll
            for (int nt = 0; nt < 2; ++nt) {
                const float* bb = Bc + (wn * 16 + nt * 8 + ld) * BP + ks * 8 + l4;
                uint32_t bh0 = fbits(bb[0]), bh1 = fbits(bb[4]);
                uint32_t bl0 = fbits(bb[PLANE]), bl1 = fbits(bb[PLANE + 4]);
#pragma unroll
                for (int mt = 0; mt < 2; ++mt) {
                    mma_tf32(acc[mt][nt], ah[mt], bh0, bh1);   // Ah*Bh
                    mma_tf32(acc[mt][nt], ah[mt], bl0, bl1);   // Ah*Bl
                    mma_tf32(acc[mt][nt], al[mt], bh0, bh1);   // Al*Bh
                }
            }
        }
        __syncthreads();
        if (kc + 2 < 8) { load_a(kc + 2, kc & 1); load_b(kc + 2, kc & 1); cp_commit(); }
    }

    // epilogue: out[t][b][o], bt = b*32 + t
#pragma unroll
    for (int mt = 0; mt < 2; ++mt) {
#pragma unroll
        for (int nt = 0; nt < 2; ++nt) {
            const int j = n0 + wn * 16 + nt * 8 + l4 * 2;
            const float b0 = __ldg(fc1_b + j), b1 = __ldg(fc1_b + j + 1);
            int btr = m0 + wm * 32 + mt * 16 + ld;
            int b = btr >> 5, t = btr & 31;
            *reinterpret_cast<float2*>(out + ((size_t)t * 32 + b) * OUTC + j) =
                make_float2(acc[mt][nt][0] + b0, acc[mt][nt][1] + b1);
            btr += 8;
            b = btr >> 5; t = btr & 31;
            *reinterpret_cast<float2*>(out + ((size_t)t * 32 + b) * OUTC + j) =
                make_float2(acc[mt][nt][2] + b0, acc[mt][nt][3] + b1);
        }
    }
}

extern "C" void kernel_launch(void* const* d_in, const int* in_sizes, int n_in,
                              void* d_out, int out_size) {
    const float* x     = (const float*)d_in[0];  // (32,32,64,512)
    const float* ue_w  = (const float*)d_in[1];  // (64,512)
    const float* ue_b  = (const float*)d_in[2];  // (64,)
    const float* be    = (const float*)d_in[3];  // (64,)
    const float* w_w   = (const float*)d_in[4];  // (1,64)
    // d_in[5] = w_b: softmax-invariant, dropped
    const float* fc1_w = (const float*)d_in[6];  // (256,512)
    const float* fc1_b = (const float*)d_in[7];  // (256,)
    float* out = (float*)d_out;                  // [T][B][256]

    prep_split<<<640, 256>>>(ue_w, fc1_w);

    cudaFuncSetAttribute(stattn_main, cudaFuncAttributeMaxDynamicSharedMemorySize, SMEM_MAIN_BYTES);
    stattn_main<<<BT, 256, SMEM_MAIN_BYTES>>>(x, ue_b, be, w_w);

    cudaFuncSetAttribute(stattn_fc, cudaFuncAttributeMaxDynamicSharedMemorySize, SMEM_FC_BYTES);
    stattn_fc<<<dim3(16, 4), 256, SMEM_FC_BYTES>>>(fc1_b, out);
}

// round 12
// speedup vs baseline: 1.1241x; 1.1241x over previous
#include <cuda_runtime.h>
#include <cuda_bf16.h>
#include <math.h>
#include <stdint.h>

// STAttn fused, GB300 sm_103a. Round 12 (= round 10 resubmit; broker timeouts):
// bf16 3-product mma (minimal mma count) + warp-specialized producers
// (overlap x-split with tensor) + product-major mma ordering (break dependent
// accumulator chains).
// B=32,T=32 (BT=1024), N=64, D=512, H=64, OUT=256.

#define NB 64
#define DD 512
#define HH 64
#define OUTC 256
#define BT 1024
#define XP 520         // x smem pitch in bf16 (512+8): conflict-free frags
#define WP 136         // weight-chunk pitch in bf16 (128+8)
#define KCHUNK 128

#define WBUF_BF16 (2 * HH * WP)             // one buffer: hi plane + lo plane
// main smem: XH(64*520) XL(64*520) bf16 | Wbuf[2] bf16 | 256 floats
#define SMEM1_BF16 (2 * NB * XP + 2 * WBUF_BF16)
#define SMEM1_BYTES (SMEM1_BF16 * 2 + 256 * 4)
// fc smem: AH+AL (64*520 each) | Wbuf[2]
#define SMEMF_BYTES ((2 * NB * XP + 2 * WBUF_BF16) * 2)

__device__ __align__(16) __nv_bfloat16 g_uew_h[HH * DD];
__device__ __align__(16) __nv_bfloat16 g_uew_l[HH * DD];
__device__ __align__(16) __nv_bfloat16 g_fc1_h[OUTC * DD];
__device__ __align__(16) __nv_bfloat16 g_fc1_l[OUTC * DD];
__device__ __align__(16) __nv_bfloat16 g_attr_h[BT * DD];
__device__ __align__(16) __nv_bfloat16 g_attr_l[BT * DD];

// ---------------- helpers ----------------
__device__ __forceinline__ uint32_t ld_u32(const void* p) {
    return *reinterpret_cast<const uint32_t*>(p);
}
__device__ __forceinline__ void cp_async16(uint32_t s, const void* g) {
    asm volatile("cp.async.cg.shared.global [%0], [%1], 16;\n" :: "r"(s), "l"(g));
}
__device__ __forceinline__ void cp_commit() { asm volatile("cp.async.commit_group;\n"); }
template <int N> __device__ __forceinline__ void cp_wait() {
    asm volatile("cp.async.wait_group %0;\n" :: "n"(N));
}
__device__ __forceinline__ uint32_t smem_u32(const void* p) {
    uint32_t a;
    asm("{ .reg .u64 t; cvta.to.shared.u64 t, %1; cvt.u32.u64 %0, t; }" : "=r"(a) : "l"(p));
    return a;
}
__device__ __forceinline__ void split1(float v, __nv_bfloat16& h, __nv_bfloat16& l) {
    h = __float2bfloat16(v);
    l = __float2bfloat16(v - __bfloat162float(h));
}
__device__ __forceinline__ void split2(float a, float b, uint32_t& hp, uint32_t& lp) {
    __nv_bfloat16 hx, hy, lx, ly;
    split1(a, hx, lx);
    split1(b, hy, ly);
    __nv_bfloat162 h2 = __halves2bfloat162(hx, hy);
    __nv_bfloat162 l2 = __halves2bfloat162(lx, ly);
    hp = *reinterpret_cast<uint32_t*>(&h2);
    lp = *reinterpret_cast<uint32_t*>(&l2);
}
__device__ __forceinline__ void mma_bf16(float* d,
                                         uint32_t a0, uint32_t a1, uint32_t a2, uint32_t a3,
                                         uint32_t b0, uint32_t b1) {
    asm volatile(
        "mma.sync.aligned.m16n8k16.row.col.f32.bf16.bf16.f32 "
        "{%0,%1,%2,%3}, {%4,%5,%6,%7}, {%8,%9}, {%0,%1,%2,%3};\n"
        : "+f"(d[0]), "+f"(d[1]), "+f"(d[2]), "+f"(d[3])
        : "r"(a0), "r"(a1), "r"(a2), "r"(a3), "r"(b0), "r"(b1));
}

// ---------------- prep: split weights to bf16 hi/lo once ----------------
__global__ __launch_bounds__(256)
void prep_split(const float* __restrict__ ue_w, const float* __restrict__ fc1_w) {
    int i = blockIdx.x * 256 + threadIdx.x;   // one float4 per thread
    const int n_ue = HH * DD / 4;             // 8192
    if (i >= n_ue + OUTC * DD / 4) return;
    const float* src;
    __nv_bfloat16 *dh, *dl;
    int k;
    if (i < n_ue) { src = ue_w; dh = g_uew_h; dl = g_uew_l; k = i; }
    else { src = fc1_w; dh = g_fc1_h; dl = g_fc1_l; k = i - n_ue; }
    float4 v = *reinterpret_cast<const float4*>(src + k * 4);
    uint32_t h0, l0, h1, l1;
    split2(v.x, v.y, h0, l0);
    split2(v.z, v.w, h1, l1);
    *reinterpret_cast<uint2*>(dh + k * 4) = make_uint2(h0, h1);
    *reinterpret_cast<uint2*>(dl + k * 4) = make_uint2(l0, l1);
}

// ---------------- kernel 1: per-bt CTA, 512 threads ----------------
// warps 0-7: mma consumers (round-2 64x64 layout). warps 8-15: producers
// (x LDG fp32 -> split bf16 hi/lo -> STS; W cp.async double-buffered).
__global__ __launch_bounds__(512, 1)
void stattn_main(const float* __restrict__ x,
                 const float* __restrict__ ue_b,
                 const float* __restrict__ be,
                 const float* __restrict__ w_w) {
    extern __shared__ __nv_bfloat16 sm[];
    __nv_bfloat16* XHs = sm;
    __nv_bfloat16* XLs = sm + NB * XP;
    __nv_bfloat16* Wb  = sm + 2 * NB * XP;          // 2 x (WH 64*136 | WL 64*136)
    float* fbase  = reinterpret_cast<float*>(sm + SMEM1_BF16);
    float* bias_s = fbase;        // 64
    float* ww_s   = fbase + 64;   // 64
    float* e_s    = fbase + 128;  // 64
    float* a_s    = fbase + 192;  // 64

    const int tid  = threadIdx.x;
    const int lane = tid & 31;
    const int warp = tid >> 5;
    const bool consumer = warp < 8;
    const int ptid = tid - 256;            // producer-local tid (0..255)
    const int bt = blockIdx.x;

    if (tid < 64) {
        e_s[tid]    = 0.0f;
        bias_s[tid] = ue_b[tid] + be[tid];
        ww_s[tid]   = w_w[tid];
    }

    const float* xg = x + (size_t)bt * (NB * DD);

    // producer: convert x chunk kc (64 rows x 128 cols fp32) into XH/XL cols
    auto convert = [&](int kc) {
#pragma unroll
        for (int it = 0; it < 8; ++it) {
            int idx = ptid + it * 256;
            int n = idx >> 5, q = idx & 31, c = kc * KCHUNK + q * 4;
            float4 v = __ldg(reinterpret_cast<const float4*>(xg + n * DD + c));
            uint32_t h0, l0, h1, l1;
            split2(v.x, v.y, h0, l0);
            split2(v.z, v.w, h1, l1);
            *reinterpret_cast<uint2*>(XHs + n * XP + c) = make_uint2(h0, h1);
            *reinterpret_cast<uint2*>(XLs + n * XP + c) = make_uint2(l0, l1);
        }
    };
    // producer: cp.async W chunk kc (bf16 hi+lo) into buffer buf
    auto load_w = [&](int kc, int buf) {
        __nv_bfloat16* WH = Wb + buf * WBUF_BF16;
        __nv_bfloat16* WL = WH + HH * WP;
#pragma unroll
        for (int it = 0; it < 4; ++it) {
            int idx = ptid + it * 256;
            int j = idx >> 4, q = idx & 15;
            const __nv_bfloat16* s = g_uew_h + j * DD + kc * KCHUNK + q * 8;
            cp_async16(smem_u32(WH + j * WP + q * 8), s);
            cp_async16(smem_u32(WL + j * WP + q * 8), s + (g_uew_l - g_uew_h));
        }
    };

    // prologue: producers stage chunk 0
    if (!consumer) {
        load_w(0, 0); cp_commit();
        convert(0);
        cp_wait<0>();
    }
    __syncthreads();

    // consumer tile mapping (8 warps over 64x64): wm 16-row, wn 32-col blocks
    const int wm = warp & 3;
    const int wn = (warp >> 2) & 1;
    const int r  = wm * 16 + (lane >> 2);
    const int qk = (lane & 3) * 2;

    float acc[4][4];
#pragma unroll
    for (int i = 0; i < 4; ++i)
#pragma unroll
        for (int j = 0; j < 4; ++j) acc[i][j] = 0.0f;

#pragma unroll
    for (int kc = 0; kc < 4; ++kc) {
        if (consumer) {
            const __nv_bfloat16* WH = Wb + (kc & 1) * WBUF_BF16;
            const __nv_bfloat16* WL = WH + HH * WP;
#pragma unroll
            for (int kk = 0; kk < 8; ++kk) {
                const int kg = kc * KCHUNK + kk * 16 + qk;
                const int kl = kk * 16 + qk;
                const __nv_bfloat16* pa  = XHs + r * XP + kg;
                const __nv_bfloat16* pal = XLs + r * XP + kg;
                uint32_t ah0 = ld_u32(pa);
                uint32_t ah1 = ld_u32(pa + 8 * XP);
                uint32_t ah2 = ld_u32(pa + 8);
                uint32_t ah3 = ld_u32(pa + 8 * XP + 8);
                uint32_t al0 = ld_u32(pal);
                uint32_t al1 = ld_u32(pal + 8 * XP);
                uint32_t al2 = ld_u32(pal + 8);
                uint32_t al3 = ld_u32(pal + 8 * XP + 8);
                uint32_t bh[4][2], bl[4][2];
#pragma unroll
                for (int jt = 0; jt < 4; ++jt) {
                    const int jb = wn * 32 + jt * 8 + (lane >> 2);
                    const __nv_bfloat16* pb  = WH + jb * WP + kl;
                    const __nv_bfloat16* pbl = WL + jb * WP + kl;
                    bh[jt][0] = ld_u32(pb);
                    bh[jt][1] = ld_u32(pb + 8);
                    bl[jt][0] = ld_u32(pbl);
                    bl[jt][1] = ld_u32(pbl + 8);
                }
                // product-major ordering: same-acc mma are 4 apart (ILP)
#pragma unroll
                for (int jt = 0; jt < 4; ++jt)
                    mma_bf16(acc[jt], ah0, ah1, ah2, ah3, bh[jt][0], bh[jt][1]);  // hi*hi
#pragma unroll
                for (int jt = 0; jt < 4; ++jt)
                    mma_bf16(acc[jt], ah0, ah1, ah2, ah3, bl[jt][0], bl[jt][1]);  // hi*lo
#pragma unroll
                for (int jt = 0; jt < 4; ++jt)
                    mma_bf16(acc[jt], al0, al1, al2, al3, bh[jt][0], bh[jt][1]);  // lo*hi
            }
        } else if (kc < 3) {
            load_w(kc + 1, (kc + 1) & 1); cp_commit();
            convert(kc + 1);
            cp_wait<0>();
        }
        __syncthreads();
    }

    // ---- epilogue: bias + leaky_relu(0.2) + dot w_w -> e[64] (consumers) ----
    if (consumer) {
        float pe0 = 0.0f, pe1 = 0.0f;
#pragma unroll
        for (int jt = 0; jt < 4; ++jt) {
            const int j = wn * 32 + jt * 8 + qk;
            float v;
            v = acc[jt][0] + bias_s[j];     v = (v < 0.0f) ? 0.2f * v : v; pe0 = fmaf(ww_s[j],     v, pe0);
            v = acc[jt][1] + bias_s[j + 1]; v = (v < 0.0f) ? 0.2f * v : v; pe0 = fmaf(ww_s[j + 1], v, pe0);
            v = acc[jt][2] + bias_s[j];     v = (v < 0.0f) ? 0.2f * v : v; pe1 = fmaf(ww_s[j],     v, pe1);
            v = acc[jt][3] + bias_s[j + 1]; v = (v < 0.0f) ? 0.2f * v : v; pe1 = fmaf(ww_s[j + 1], v, pe1);
        }
        atomicAdd(&e_s[r], pe0);
        atomicAdd(&e_s[r + 8], pe1);
    }
    __syncthreads();

    // ---- softmax over N=64 (w_b softmax-invariant, dropped) ----
    if (warp == 0) {
        float e0 = e_s[lane], e1 = e_s[lane + 32];
        float mx = fmaxf(e0, e1);
#pragma unroll
        for (int o = 16; o; o >>= 1) mx = fmaxf(mx, __shfl_xor_sync(0xffffffffu, mx, o));
        float x0 = expf(e0 - mx), x1 = expf(e1 - mx);
        float s = x0 + x1;
#pragma unroll
        for (int o = 16; o; o >>= 1) s += __shfl_xor_sync(0xffffffffu, s, o);
        float inv = 1.0f / s;
        a_s[lane]      = x0 * inv;
        a_s[lane + 32] = x1 * inv;
    }
    __syncthreads();

    // ---- pooling: 512 threads, one d-column each; x = hi+lo (2^-18 exact) ----
    {
        float s = 0.0f;
#pragma unroll 8
        for (int n = 0; n < NB; ++n) {
            float h = __bfloat162float(XHs[n * XP + tid]);
            float l = __bfloat162float(XLs[n * XP + tid]);
            s = fmaf(a_s[n], h + l, s);
        }
        __nv_bfloat16 hh, ll;
        split1(s, hh, ll);
        g_attr_h[bt * DD + tid] = hh;
        g_attr_l[bt * DD + tid] = ll;
    }
}

// ---------------- kernel 2: fc = attr @ fc1_w^T + b, out[t][b][o] ----------------
__global__ __launch_bounds__(256, 1)
void stattn_fc(const float* __restrict__ fc1_b, float* __restrict__ out) {
    extern __shared__ __nv_bfloat16 smb[];
    __nv_bfloat16* AHs = smb;                 // 64 x 520
    __nv_bfloat16* ALs = smb + NB * XP;
    __nv_bfloat16* Wb  = smb + 2 * NB * XP;   // 2 x (WH | WL)

    const int tid  = threadIdx.x;
    const int lane = tid & 31;
    const int warp = tid >> 5;
    const int wm   = warp & 3;
    const int wn   = warp >> 2;
    const int m0   = blockIdx.x * 64;   // bt tile
    const int n0   = blockIdx.y * 64;   // out-col tile

    auto load_a = [&](int kc) {
#pragma unroll
        for (int it = 0; it < 4; ++it) {
            int idx = tid + it * 256;
            int n = idx >> 4, q = idx & 15;
            const __nv_bfloat16* s = g_attr_h + (m0 + n) * DD + kc * KCHUNK + q * 8;
            cp_async16(smem_u32(AHs + n * XP + kc * KCHUNK + q * 8), s);
            cp_async16(smem_u32(ALs + n * XP + kc * KCHUNK + q * 8), s + (g_attr_l - g_attr_h));
        }
    };
    auto load_w = [&](int kc, int buf) {
        __nv_bfloat16* WH = Wb + buf * WBUF_BF16;
        __nv_bfloat16* WL = WH + HH * WP;
#pragma unroll
        for (int it = 0; it < 4; ++it) {
            int idx = tid + it * 256;
            int j = idx >> 4, q = idx & 15;
            const __nv_bfloat16* s = g_fc1_h + (n0 + j) * DD + kc * KCHUNK + q * 8;
            cp_async16(smem_u32(WH + j * WP + q * 8), s);
            cp_async16(smem_u32(WL + j * WP + q * 8), s + (g_fc1_l - g_fc1_h));
        }
    };

    load_a(0); load_w(0, 0); cp_commit();
    load_a(1); load_w(1, 1); cp_commit();

    float acc[4][4];
#pragma unroll
    for (int i = 0; i < 4; ++i)
#pragma unroll
        for (int j = 0; j < 4; ++j) acc[i][j] = 0.0f;

    const int r  = wm * 16 + (lane >> 2);
    const int qk = (lane & 3) * 2;

#pragma unroll
    for (int kc = 0; kc < 4; ++kc) {
        if (kc < 3) cp_wait<1>(); else cp_wait<0>();
        __syncthreads();

        const __nv_bfloat16* WH = Wb + (kc & 1) * WBUF_BF16;
        const __nv_bfloat16* WL = WH + HH * WP;

#pragma unroll
        for (int kk = 0; kk < 8; ++kk) {
            const int kg = kc * KCHUNK + kk * 16 + qk;
            const int kl = kk * 16 + qk;
            const __nv_bfloat16* pa  = AHs + r * XP + kg;
            const __nv_bfloat16* pal = ALs + r * XP + kg;
            uint32_t ah0 = ld_u32(pa);
            uint32_t ah1 = ld_u32(pa + 8 * XP);
            uint32_t ah2 = ld_u32(pa + 8);
            uint32_t ah3 = ld_u32(pa + 8 * XP + 8);
            uint32_t al0 = ld_u32(pal);
            uint32_t al1 = ld_u32(pal + 8 * XP);
            uint32_t al2 = ld_u32(pal + 8);
            uint32_t al3 = ld_u32(pal + 8 * XP + 8);
            uint32_t bh[4][2], bl[4][2];
#pragma unroll
            for (int jt = 0; jt < 4; ++jt) {
                const int jb = wn * 32 + jt * 8 + (lane >> 2);
                const __nv_bfloat16* pb  = WH + jb * WP + kl;
                const __nv_bfloat16* pbl = WL + jb * WP + kl;
                bh[jt][0] = ld_u32(pb);
                bh[jt][1] = ld_u32(pb + 8);
                bl[jt][0] = ld_u32(pbl);
                bl[jt][1] = ld_u32(pbl + 8);
            }
#pragma unroll
            for (int jt = 0; jt < 4; ++jt)
                mma_bf16(acc[jt], ah0, ah1, ah2, ah3, bh[jt][0], bh[jt][1]);
#pragma unroll
            for (int jt = 0; jt < 4; ++jt)
                mma_bf16(acc[jt], ah0, ah1, ah2, ah3, bl[jt][0], bl[jt][1]);
#pragma unroll
            for (int jt = 0; jt < 4; ++jt)
                mma_bf16(acc[jt], al0, al1, al2, al3, bh[jt][0], bh[jt][1]);
        }
        __syncthreads();
        if (kc + 2 < 4) { load_a(kc + 2); load_w(kc + 2, kc & 1); cp_commit(); }
    }

    // epilogue: rows {r, r+8} (bt), cols {j, j+1} (out). out[t][b][o], bt=b*32+t.
#pragma unroll
    for (int jt = 0; jt < 4; ++jt) {
        const int j = n0 + wn * 32 + jt * 8 + qk;
        const float b0 = __ldg(fc1_b + j), b1 = __ldg(fc1_b + j + 1);
        int btr = m0 + r;
        int b = btr >> 5, t = btr & 31;
        float* o0 = out + ((size_t)t * 32 + b) * OUTC + j;
        o0[0] = acc[jt][0] + b0;
        o0[1] = acc[jt][1] + b1;
        btr = m0 + r + 8;
        b = btr >> 5; t = btr & 31;
        float* o1 = out + ((size_t)t * 32 + b) * OUTC + j;
        o1[0] = acc[jt][2] + b0;
        o1[1] = acc[jt][3] + b1;
    }
}

extern "C" void kernel_launch(void* const* d_in, const int* in_sizes, int n_in,
                              void* d_out, int out_size) {
    const float* x     = (const float*)d_in[0];  // (32,32,64,512)
    const float* ue_w  = (const float*)d_in[1];  // (64,512)
    const float* ue_b  = (const float*)d_in[2];  // (64,)
    const float* be    = (const float*)d_in[3];  // (64,)
    const float* w_w   = (const float*)d_in[4];  // (1,64)
    // d_in[5] = w_b: softmax-invariant, dropped
    const float* fc1_w = (const float*)d_in[6];  // (256,512)
    const float* fc1_b = (const float*)d_in[7];  // (256,)
    float* out = (float*)d_out;                  // [T][B][256]

    prep_split<<<160, 256>>>(ue_w, fc1_w);

    cudaFuncSetAttribute(stattn_main, cudaFuncAttributeMaxDynamicSharedMemorySize, SMEM1_BYTES);
    stattn_main<<<BT, 512, SMEM1_BYTES>>>(x, ue_b, be, w_w);

    cudaFuncSetAttribute(stattn_fc, cudaFuncAttributeMaxDynamicSharedMemorySize, SMEMF_BYTES);
    stattn_fc<<<dim3(16, 4), 256, SMEMF_BYTES>>>(fc1_b, out);
}

// round 14
// speedup vs baseline: 1.3556x; 1.2060x over previous
#include <cuda_runtime.h>
#include <cuda_bf16.h>
#include <math.h>
#include <stdint.h>

// STAttn fused, GB300 sm_103a. Round 14 (= round 13 resubmit; broker timeout):
// occupancy attack.
// Theory: main kernel is latency-exposed (1 CTA/SM, 2 mma-warps/SMSP, 7 waves).
// Fix: smem diet to ~103KB -> 2 CTAs/SM (4 mma warps/SMSP + cross-CTA overlap).
//   - x: double-buffered 128-col chunks (hi/lo bf16), not full-width
//   - W: single buffer, cp.async hidden behind the convert phase
//   - pooling: re-read exact fp32 x from gmem (L2-hot)
// B=32,T=32 (BT=1024), N=64, D=512, H=64, OUT=256.

#define NB 64
#define DD 512
#define HH 64
#define OUTC 256
#define BT 1024
#define KCHUNK 128

// ---- main kernel smem (bf16 units) ----
#define PCH 136                    // chunk pitch (128+8) -> conflict-free
#define PLANE_BF (64 * PCH)        // 8704 bf16: one 64x128 plane
#define XBUF_BF (2 * PLANE_BF)     // hi+lo, one x chunk buffer
#define WB_OFF (2 * XBUF_BF)       // x double buffer before W
#define MISC_BF (WB_OFF + XBUF_BF) // 52224 bf16
#define SMEM_MAIN_BYTES (MISC_BF * 2 + 256 * 4)   // 105472 B -> 2 CTAs/SM

// ---- fc kernel smem (unchanged R12 layout) ----
#define XP 520
#define WP 136
#define WBUF_BF16 (2 * HH * WP)
#define SMEMF_BYTES ((2 * NB * XP + 2 * WBUF_BF16) * 2)

__device__ __align__(16) __nv_bfloat16 g_uew_h[HH * DD];
__device__ __align__(16) __nv_bfloat16 g_uew_l[HH * DD];
__device__ __align__(16) __nv_bfloat16 g_fc1_h[OUTC * DD];
__device__ __align__(16) __nv_bfloat16 g_fc1_l[OUTC * DD];
__device__ __align__(16) __nv_bfloat16 g_attr_h[BT * DD];
__device__ __align__(16) __nv_bfloat16 g_attr_l[BT * DD];

// ---------------- helpers ----------------
__device__ __forceinline__ uint32_t ld_u32(const void* p) {
    return *reinterpret_cast<const uint32_t*>(p);
}
__device__ __forceinline__ void cp_async16(uint32_t s, const void* g) {
    asm volatile("cp.async.cg.shared.global [%0], [%1], 16;\n" :: "r"(s), "l"(g));
}
__device__ __forceinline__ void cp_commit() { asm volatile("cp.async.commit_group;\n"); }
template <int N> __device__ __forceinline__ void cp_wait() {
    asm volatile("cp.async.wait_group %0;\n" :: "n"(N));
}
__device__ __forceinline__ uint32_t smem_u32(const void* p) {
    uint32_t a;
    asm("{ .reg .u64 t; cvta.to.shared.u64 t, %1; cvt.u32.u64 %0, t; }" : "=r"(a) : "l"(p));
    return a;
}
__device__ __forceinline__ void split1(float v, __nv_bfloat16& h, __nv_bfloat16& l) {
    h = __float2bfloat16(v);
    l = __float2bfloat16(v - __bfloat162float(h));
}
__device__ __forceinline__ void split2(float a, float b, uint32_t& hp, uint32_t& lp) {
    __nv_bfloat16 hx, hy, lx, ly;
    split1(a, hx, lx);
    split1(b, hy, ly);
    __nv_bfloat162 h2 = __halves2bfloat162(hx, hy);
    __nv_bfloat162 l2 = __halves2bfloat162(lx, ly);
    hp = *reinterpret_cast<uint32_t*>(&h2);
    lp = *reinterpret_cast<uint32_t*>(&l2);
}
__device__ __forceinline__ void mma_bf16(float* d,
                                         uint32_t a0, uint32_t a1, uint32_t a2, uint32_t a3,
                                         uint32_t b0, uint32_t b1) {
    asm volatile(
        "mma.sync.aligned.m16n8k16.row.col.f32.bf16.bf16.f32 "
        "{%0,%1,%2,%3}, {%4,%5,%6,%7}, {%8,%9}, {%0,%1,%2,%3};\n"
        : "+f"(d[0]), "+f"(d[1]), "+f"(d[2]), "+f"(d[3])
        : "r"(a0), "r"(a1), "r"(a2), "r"(a3), "r"(b0), "r"(b1));
}

// ---------------- prep: split weights to bf16 hi/lo once ----------------
__global__ __launch_bounds__(256)
void prep_split(const float* __restrict__ ue_w, const float* __restrict__ fc1_w) {
    int i = blockIdx.x * 256 + threadIdx.x;   // one float4 per thread
    const int n_ue = HH * DD / 4;             // 8192
    if (i >= n_ue + OUTC * DD / 4) return;
    const float* src;
    __nv_bfloat16 *dh, *dl;
    int k;
    if (i < n_ue) { src = ue_w; dh = g_uew_h; dl = g_uew_l; k = i; }
    else { src = fc1_w; dh = g_fc1_h; dl = g_fc1_l; k = i - n_ue; }
    float4 v = *reinterpret_cast<const float4*>(src + k * 4);
    uint32_t h0, l0, h1, l1;
    split2(v.x, v.y, h0, l0);
    split2(v.z, v.w, h1, l1);
    *reinterpret_cast<uint2*>(dh + k * 4) = make_uint2(h0, h1);
    *reinterpret_cast<uint2*>(dl + k * 4) = make_uint2(l0, l1);
}

// ---------------- kernel 1: per-bt CTA, 256 threads, 2 CTAs/SM ----------------
__global__ __launch_bounds__(256, 2)
void stattn_main(const float* __restrict__ x,
                 const float* __restrict__ ue_b,
                 const float* __restrict__ be,
                 const float* __restrict__ w_w) {
    extern __shared__ __nv_bfloat16 sm[];
    __nv_bfloat16* XB = sm;                     // [2 bufs][hi|lo][64][136]
    __nv_bfloat16* WB = sm + WB_OFF;            // [hi|lo][64][136], single buffer
    float* fbase  = reinterpret_cast<float*>(sm + MISC_BF);
    float* bias_s = fbase;        // 64
    float* ww_s   = fbase + 64;   // 64
    float* e_s    = fbase + 128;  // 64
    float* a_s    = fbase + 192;  // 64

    const int tid  = threadIdx.x;
    const int lane = tid & 31;
    const int warp = tid >> 5;
    const int bt   = blockIdx.x;

    if (tid < 64) {
        e_s[tid]    = 0.0f;
        bias_s[tid] = ue_b[tid] + be[tid];
        ww_s[tid]   = w_w[tid];
    }

    const float* xg = x + (size_t)bt * (NB * DD);

    // convert x chunk kc (64 x 128 fp32) -> xbuf[buf] hi/lo bf16
    auto convert = [&](int kc, int buf) {
        __nv_bfloat16* XH = XB + buf * XBUF_BF;
        __nv_bfloat16* XL = XH + PLANE_BF;
#pragma unroll
        for (int it = 0; it < 8; ++it) {
            int idx = tid + it * 256;
            int n = idx >> 5, q = idx & 31;
            float4 v = __ldg(reinterpret_cast<const float4*>(xg + n * DD + kc * KCHUNK + q * 4));
            uint32_t h0, l0, h1, l1;
            split2(v.x, v.y, h0, l0);
            split2(v.z, v.w, h1, l1);
            *reinterpret_cast<uint2*>(XH + n * PCH + q * 4) = make_uint2(h0, h1);
            *reinterpret_cast<uint2*>(XL + n * PCH + q * 4) = make_uint2(l0, l1);
        }
    };
    // cp.async W chunk kc into the single W buffer (hi+lo planes)
    auto load_w = [&](int kc) {
#pragma unroll
        for (int it = 0; it < 4; ++it) {
            int idx = tid + it * 256;
            int j = idx >> 4, q = idx & 15;
            const __nv_bfloat16* s = g_uew_h + j * DD + kc * KCHUNK + q * 8;
            cp_async16(smem_u32(WB + j * PCH + q * 8), s);
            cp_async16(smem_u32(WB + PLANE_BF + j * PCH + q * 8), s + (g_uew_l - g_uew_h));
        }
    };

    // prologue: stage chunk 0
    load_w(0); cp_commit();
    convert(0, 0);

    // 8 warps over 64x64 output: wm 16-row blocks, wn 32-col blocks
    const int wm = warp & 3;
    const int wn = warp >> 2;
    const int r  = wm * 16 + (lane >> 2);
    const int qk = (lane & 3) * 2;

    float acc[4][4];
#pragma unroll
    for (int i = 0; i < 4; ++i)
#pragma unroll
        for (int j = 0; j < 4; ++j) acc[i][j] = 0.0f;

#pragma unroll
    for (int kc = 0; kc < 4; ++kc) {
        cp_wait<0>();
        __syncthreads();    // W(kc) + xbuf(kc&1) visible to all

        const __nv_bfloat16* XH = XB + (kc & 1) * XBUF_BF;
        const __nv_bfloat16* XL = XH + PLANE_BF;
        const __nv_bfloat16* WH = WB;
        const __nv_bfloat16* WL = WB + PLANE_BF;

#pragma unroll
        for (int kk = 0; kk < 8; ++kk) {
            const int kl = kk * 16 + qk;   // chunk-local column
            const __nv_bfloat16* pa  = XH + r * PCH + kl;
            const __nv_bfloat16* pal = XL + r * PCH + kl;
            uint32_t ah0 = ld_u32(pa);
            uint32_t ah1 = ld_u32(pa + 8 * PCH);
            uint32_t ah2 = ld_u32(pa + 8);
            uint32_t ah3 = ld_u32(pa + 8 * PCH + 8);
            uint32_t al0 = ld_u32(pal);
            uint32_t al1 = ld_u32(pal + 8 * PCH);
            uint32_t al2 = ld_u32(pal + 8);
            uint32_t al3 = ld_u32(pal + 8 * PCH + 8);
            uint32_t bh[4][2], bl[4][2];
#pragma unroll
            for (int jt = 0; jt < 4; ++jt) {
                const int jb = wn * 32 + jt * 8 + (lane >> 2);
                const __nv_bfloat16* pb  = WH + jb * PCH + kl;
                const __nv_bfloat16* pbl = WL + jb * PCH + kl;
                bh[jt][0] = ld_u32(pb);
                bh[jt][1] = ld_u32(pb + 8);
                bl[jt][0] = ld_u32(pbl);
                bl[jt][1] = ld_u32(pbl + 8);
            }
#pragma unroll
            for (int jt = 0; jt < 4; ++jt)
                mma_bf16(acc[jt], ah0, ah1, ah2, ah3, bh[jt][0], bh[jt][1]);  // hi*hi
#pragma unroll
            for (int jt = 0; jt < 4; ++jt)
                mma_bf16(acc[jt], ah0, ah1, ah2, ah3, bl[jt][0], bl[jt][1]);  // hi*lo
#pragma unroll
            for (int jt = 0; jt < 4; ++jt)
                mma_bf16(acc[jt], al0, al1, al2, al3, bh[jt][0], bh[jt][1]);  // lo*hi
        }
        __syncthreads();    // everyone done reading W buffer (and old xbuf free)
        if (kc < 3) {
            load_w(kc + 1); cp_commit();        // W refill hidden behind convert
            convert(kc + 1, (kc + 1) & 1);
        }
    }

    // ---- epilogue: bias + leaky_relu(0.2) + dot w_w -> e[64] ----
    {
        float pe0 = 0.0f, pe1 = 0.0f;
#pragma unroll
        for (int jt = 0; jt < 4; ++jt) {
            const int j = wn * 32 + jt * 8 + qk;
            float v;
            v = acc[jt][0] + bias_s[j];     v = (v < 0.0f) ? 0.2f * v : v; pe0 = fmaf(ww_s[j],     v, pe0);
            v = acc[jt][1] + bias_s[j + 1]; v = (v < 0.0f) ? 0.2f * v : v; pe0 = fmaf(ww_s[j + 1], v, pe0);
            v = acc[jt][2] + bias_s[j];     v = (v < 0.0f) ? 0.2f * v : v; pe1 = fmaf(ww_s[j],     v, pe1);
            v = acc[jt][3] + bias_s[j + 1]; v = (v < 0.0f) ? 0.2f * v : v; pe1 = fmaf(ww_s[j + 1], v, pe1);
        }
        atomicAdd(&e_s[r], pe0);
        atomicAdd(&e_s[r + 8], pe1);
    }
    __syncthreads();

    // ---- softmax over N=64 (w_b softmax-invariant, dropped) ----
    if (warp == 0) {
        float e0 = e_s[lane], e1 = e_s[lane + 32];
        float mx = fmaxf(e0, e1);
#pragma unroll
        for (int o = 16; o; o >>= 1) mx = fmaxf(mx, __shfl_xor_sync(0xffffffffu, mx, o));
        float x0 = expf(e0 - mx), x1 = expf(e1 - mx);
        float s = x0 + x1;
#pragma unroll
        for (int o = 16; o; o >>= 1) s += __shfl_xor_sync(0xffffffffu, s, o);
        float inv = 1.0f / s;
        a_s[lane]      = x0 * inv;
        a_s[lane + 32] = x1 * inv;
    }
    __syncthreads();

    // ---- pooling: re-read exact fp32 x from gmem (L2-hot); 2 cols/thread ----
    {
        const int d0 = 2 * tid;
        float s0 = 0.0f, s1 = 0.0f;
#pragma unroll 8
        for (int n = 0; n < NB; ++n) {
            float2 v = __ldg(reinterpret_cast<const float2*>(xg + n * DD + d0));
            float an = a_s[n];
            s0 = fmaf(an, v.x, s0);
            s1 = fmaf(an, v.y, s1);
        }
        uint32_t hp, lp;
        split2(s0, s1, hp, lp);
        *reinterpret_cast<uint32_t*>(g_attr_h + bt * DD + d0) = hp;
        *reinterpret_cast<uint32_t*>(g_attr_l + bt * DD + d0) = lp;
    }
}

// ---------------- kernel 2: fc = attr @ fc1_w^T + b, out[t][b][o] ----------------
__global__ __launch_bounds__(256, 1)
void stattn_fc(const float* __restrict__ fc1_b, float* __restrict__ out) {
    extern __shared__ __nv_bfloat16 smb[];
    __nv_bfloat16* AHs = smb;                 // 64 x 520
    __nv_bfloat16* ALs = smb + NB * XP;
    __nv_bfloat16* Wb  = smb + 2 * NB * XP;   // 2 x (WH | WL)

    const int tid  = threadIdx.x;
    const int lane = tid & 31;
    const int warp = tid >> 5;
    const int wm   = warp & 3;
    const int wn   = warp >> 2;
    const int m0   = blockIdx.x * 64;   // bt tile
    const int n0   = blockIdx.y * 64;   // out-col tile

    auto load_a = [&](int kc) {
#pragma unroll
        for (int it = 0; it < 4; ++it) {
            int idx = tid + it * 256;
            int n = idx >> 4, q = idx & 15;
            const __nv_bfloat16* s = g_attr_h + (m0 + n) * DD + kc * KCHUNK + q * 8;
            cp_async16(smem_u32(AHs + n * XP + kc * KCHUNK + q * 8), s);
            cp_async16(smem_u32(ALs + n * XP + kc * KCHUNK + q * 8), s + (g_attr_l - g_attr_h));
        }
    };
    auto load_w = [&](int kc, int buf) {
        __nv_bfloat16* WH = Wb + buf * WBUF_BF16;
        __nv_bfloat16* WL = WH + HH * WP;
#pragma unroll
        for (int it = 0; it < 4; ++it) {
            int idx = tid + it * 256;
            int j = idx >> 4, q = idx & 15;
            const __nv_bfloat16* s = g_fc1_h + (n0 + j) * DD + kc * KCHUNK + q * 8;
            cp_async16(smem_u32(WH + j * WP + q * 8), s);
            cp_async16(smem_u32(WL + j * WP + q * 8), s + (g_fc1_l - g_fc1_h));
        }
    };

    load_a(0); load_w(0, 0); cp_commit();
    load_a(1); load_w(1, 1); cp_commit();

    float acc[4][4];
#pragma unroll
    for (int i = 0; i < 4; ++i)
#pragma unroll
        for (int j = 0; j < 4; ++j) acc[i][j] = 0.0f;

    const int r  = wm * 16 + (lane >> 2);
    const int qk = (lane & 3) * 2;

#pragma unroll
    for (int kc = 0; kc < 4; ++kc) {
        if (kc < 3) cp_wait<1>(); else cp_wait<0>();
        __syncthreads();

        const __nv_bfloat16* WH = Wb + (kc & 1) * WBUF_BF16;
        const __nv_bfloat16* WL = WH + HH * WP;

#pragma unroll
        for (int kk = 0; kk < 8; ++kk) {
            const int kg = kc * KCHUNK + kk * 16 + qk;
            const int kl = kk * 16 + qk;
            const __nv_bfloat16* pa  = AHs + r * XP + kg;
            const __nv_bfloat16* pal = ALs + r * XP + kg;
            uint32_t ah0 = ld_u32(pa);
            uint32_t ah1 = ld_u32(pa + 8 * XP);
            uint32_t ah2 = ld_u32(pa + 8);
            uint32_t ah3 = ld_u32(pa + 8 * XP + 8);
            uint32_t al0 = ld_u32(pal);
            uint32_t al1 = ld_u32(pal + 8 * XP);
            uint32_t al2 = ld_u32(pal + 8);
            uint32_t al3 = ld_u32(pal + 8 * XP + 8);
            uint32_t bh[4][2], bl[4][2];
#pragma unroll
            for (int jt = 0; jt < 4; ++jt) {
                const int jb = wn * 32 + jt * 8 + (lane >> 2);
                const __nv_bfloat16* pb  = WH + jb * WP + kl;
                const __nv_bfloat16* pbl = WL + jb * WP + kl;
                bh[jt][0] = ld_u32(pb);
                bh[jt][1] = ld_u32(pb + 8);
                bl[jt][0] = ld_u32(pbl);
                bl[jt][1] = ld_u32(pbl + 8);
            }
#pragma unroll
            for (int jt = 0; jt < 4; ++jt)
                mma_bf16(acc[jt], ah0, ah1, ah2, ah3, bh[jt][0], bh[jt][1]);
#pragma unroll
            for (int jt = 0; jt < 4; ++jt)
                mma_bf16(acc[jt], ah0, ah1, ah2, ah3, bl[jt][0], bl[jt][1]);
#pragma unroll
            for (int jt = 0; jt < 4; ++jt)
                mma_bf16(acc[jt], al0, al1, al2, al3, bh[jt][0], bh[jt][1]);
        }
        __syncthreads();
        if (kc + 2 < 4) { load_a(kc + 2); load_w(kc + 2, kc & 1); cp_commit(); }
    }

    // epilogue: rows {r, r+8} (bt), cols {j, j+1} (out). out[t][b][o], bt=b*32+t.
#pragma unroll
    for (int jt = 0; jt < 4; ++jt) {
        const int j = n0 + wn * 32 + jt * 8 + qk;
        const float b0 = __ldg(fc1_b + j), b1 = __ldg(fc1_b + j + 1);
        int btr = m0 + r;
        int b = btr >> 5, t = btr & 31;
        float* o0 = out + ((size_t)t * 32 + b) * OUTC + j;
        o0[0] = acc[jt][0] + b0;
        o0[1] = acc[jt][1] + b1;
        btr = m0 + r + 8;
        b = btr >> 5; t = btr & 31;
        float* o1 = out + ((size_t)t * 32 + b) * OUTC + j;
        o1[0] = acc[jt][2] + b0;
        o1[1] = acc[jt][3] + b1;
    }
}

extern "C" void kernel_launch(void* const* d_in, const int* in_sizes, int n_in,
                              void* d_out, int out_size) {
    const float* x     = (const float*)d_in[0];  // (32,32,64,512)
    const float* ue_w  = (const float*)d_in[1];  // (64,512)
    const float* ue_b  = (const float*)d_in[2];  // (64,)
    const float* be    = (const float*)d_in[3];  // (64,)
    const float* w_w   = (const float*)d_in[4];  // (1,64)
    // d_in[5] = w_b: softmax-invariant, dropped
    const float* fc1_w = (const float*)d_in[6];  // (256,512)
    const float* fc1_b = (const float*)d_in[7];  // (256,)
    float* out = (float*)d_out;                  // [T][B][256]

    prep_split<<<160, 256>>>(ue_w, fc1_w);

    cudaFuncSetAttribute(stattn_main, cudaFuncAttributeMaxDynamicSharedMemorySize, SMEM_MAIN_BYTES);
    stattn_main<<<BT, 256, SMEM_MAIN_BYTES>>>(x, ue_b, be, w_w);

    cudaFuncSetAttribute(stattn_fc, cudaFuncAttributeMaxDynamicSharedMemorySize, SMEMF_BYTES);
    stattn_fc<<<dim3(16, 4), 256, SMEMF_BYTES>>>(fc1_b, out);
}